// round 16
// baseline (speedup 1.0000x reference)
#include <cuda_runtime.h>
#include <math.h>

#define BATCH 4
#define CCH   256
#define HH    64
#define WW    64
#define HWSZ  4096
#define NCC   289   // 17*17 cost-volume channels
#define KO1   144
#define KO2   49

// ---------------- scratch (device globals; no runtime alloc) ----------------
__device__ float g_rnorm[BATCH * HWSZ];             // 1/(||f1||*256)
__device__ float g_cvpart[2][BATCH * NCC * HWSZ];   // costvol raw partials
__device__ float g_attvol[BATCH * NCC * HWSZ];      // match_vol * att
__device__ float g_h1[BATCH * KO1 * HWSZ];          // after agg1 conv + relu
__device__ float g_part[6][BATCH * KO1 * HWSZ];     // conv split-K partials

// packed fp32x2 FMA: acc += a * b (elementwise on both 32-bit lanes)
__device__ __forceinline__ void fma2(unsigned long long& acc,
                                     unsigned long long a,
                                     unsigned long long b) {
    asm("fma.rn.f32x2 %0, %1, %2, %0;" : "+l"(acc) : "l"(a), "l"(b));
}
__device__ __forceinline__ unsigned long long bcast2(float v) {
    unsigned long long r;
    asm("mov.b64 %0, {%1, %1};" : "=l"(r) : "f"(v));
    return r;
}
__device__ __forceinline__ unsigned long long pack2(float lo, float hi) {
    unsigned long long r;
    asm("mov.b64 %0, {%1, %2};" : "=l"(r) : "f"(lo), "f"(hi));
    return r;
}

// ---------------- K0: per-pixel inverse norm of f1 --------------------------
__global__ void k_rnorm(const float* __restrict__ f1) {
    int p = blockIdx.x * blockDim.x + threadIdx.x;
    int b = p >> 12;
    int sp = p & 4095;
    const float* base = f1 + (size_t)b * CCH * HWSZ + sp;
    float s = 0.f;
#pragma unroll 8
    for (int c = 0; c < CCH; c++) {
        float v = base[c * HWSZ];
        s += v * v;
    }
    float n = fmaxf(sqrtf(s), 1e-12f);
    g_rnorm[p] = 1.f / (n * 256.f);
}

// ---------------- K1: cost volume raw partials (round-8 proven form) ---------
// 272 threads, 2-way channel split, f32x2 core. No reg cap (caps spill here).
#define CV_KC 16
__global__ __launch_bounds__(272) void k_costvol(const float* __restrict__ f1,
                                                 const float* __restrict__ f2) {
    __shared__ float x1s[CV_KC * 64];
    __shared__ float x2s[CV_KC * 24 * 25];

    int tw = blockIdx.x, th = blockIdx.y;
    int b  = blockIdx.z >> 1;
    int s  = blockIdx.z & 1;
    int h0 = th * 8, w0 = tw * 8;

    int t   = threadIdx.x;
    int oj  = t >> 4;
    int pg  = t & 15;
    int py  = pg >> 1;
    int px0 = pg & 1;

    unsigned long long acc2[4][8];
    float accS[4];
#pragma unroll
    for (int j = 0; j < 4; j++) {
        accS[j] = 0.f;
#pragma unroll
        for (int p = 0; p < 8; p++) acc2[j][p] = 0ull;
    }

    int clo = s * (CCH / 2), chi = clo + CCH / 2;
    for (int c0 = clo; c0 < chi; c0 += CV_KC) {
        __syncthreads();
        for (int i = t; i < CV_KC * 64; i += 272) {
            int cc = i >> 6, pp = i & 63;
            x1s[i] = f1[(((size_t)b * CCH + c0 + cc) * 64 + h0 + (pp >> 3)) * 64 + w0 + (pp & 7)];
        }
        for (int i = t; i < CV_KC * 24 * 24; i += 272) {
            int cc = i / 576;
            int rem = i - cc * 576;
            int r = rem / 24;
            int cx = rem - r * 24;
            int gh = h0 + r - 8, gw = w0 + cx - 8;
            float v = 0.f;
            if (gh >= 0 && gh < 64 && gw >= 0 && gw < 64)
                v = f2[(((size_t)b * CCH + c0 + cc) * 64 + gh) * 64 + gw];
            x2s[cc * 600 + r * 25 + cx] = v;
        }
        __syncthreads();

#pragma unroll 2
        for (int cc = 0; cc < CV_KC; cc++) {
            float x1v[4];
            unsigned long long x1b[4];
#pragma unroll
            for (int j = 0; j < 4; j++) {
                x1v[j] = x1s[cc * 64 + py * 8 + px0 + 2 * j];
                x1b[j] = bcast2(x1v[j]);
            }
            const float* row = &x2s[cc * 600 + (py + oj) * 25 + px0];
            float rv[23];
#pragma unroll
            for (int i = 0; i < 23; i++) rv[i] = row[i];
            unsigned long long rp[11];
#pragma unroll
            for (int k = 0; k < 11; k++) rp[k] = pack2(rv[2 * k], rv[2 * k + 1]);
#pragma unroll
            for (int j = 0; j < 4; j++) {
#pragma unroll
                for (int p = 0; p < 8; p++)
                    fma2(acc2[j][p], x1b[j], rp[j + p]);
                accS[j] += x1v[j] * rv[2 * j + 16];
            }
        }
    }

    int h = h0 + py;
    float* pout = g_cvpart[s];
#pragma unroll
    for (int j = 0; j < 4; j++) {
        int px = px0 + 2 * j;
        int w = w0 + px;
        size_t base = ((size_t)b * NCC << 12) + ((size_t)oj * 17 << 12) + h * 64 + w;
#pragma unroll
        for (int p = 0; p < 8; p++) {
            float2 v = *reinterpret_cast<float2*>(&acc2[j][p]);
            pout[base + ((size_t)(2 * p) << 12)]     = v.x;
            pout[base + ((size_t)(2 * p + 1) << 12)] = v.y;
        }
        pout[base + ((size_t)16 << 12)] = accS[j];
    }
}

// ---------------- K2: depthwise 7x7 attention + gate (fused cv combine) ------
// tile = leaky((p0+p1)*rnorm) computed on load; matchvol never materialized.
__global__ __launch_bounds__(256) void k_dw(const float* __restrict__ w7,
                                            const float* __restrict__ b7) {
    __shared__ float tile[70 * 70];
    __shared__ float wsh[49];
    int bo = blockIdx.x;
    int o = bo % NCC;
    int b = bo / NCC;
    const float* p0 = g_cvpart[0] + (size_t)bo * HWSZ;
    const float* p1 = g_cvpart[1] + (size_t)bo * HWSZ;
    const float* rn = g_rnorm + ((size_t)b << 12);
    int t = threadIdx.x;

    for (int i = t; i < 4900; i += 256) {
        int r = i / 70, c = i - r * 70;
        int gy = r - 3, gx = c - 3;
        float v = 0.f;
        if (gy >= 0 && gy < 64 && gx >= 0 && gx < 64) {
            int idx = gy * 64 + gx;
            v = (p0[idx] + p1[idx]) * rn[idx];
            v = v > 0.f ? v : 0.1f * v;
        }
        tile[i] = v;
    }
    if (t < 49) wsh[t] = w7[o * 49 + t];
    __syncthreads();

    float bv = b7[o];
    float* dst = g_attvol + (size_t)bo * HWSZ;
#pragma unroll
    for (int gg = 0; gg < 4; gg++) {
        int g = gg * 256 + t;
        int y = g >> 4;
        int x0 = (g & 15) * 4;
        float a0 = bv, a1 = bv, a2 = bv, a3 = bv;
        float mv0, mv1, mv2, mv3;
#pragma unroll
        for (int ky = 0; ky < 7; ky++) {
            const float* row = &tile[(y + ky) * 70 + x0];
            float rw[10];
#pragma unroll
            for (int i = 0; i < 10; i++) rw[i] = row[i];
            if (ky == 3) { mv0 = rw[3]; mv1 = rw[4]; mv2 = rw[5]; mv3 = rw[6]; }
#pragma unroll
            for (int kx = 0; kx < 7; kx++) {
                float wv = wsh[ky * 7 + kx];
                a0 += wv * rw[kx];
                a1 += wv * rw[kx + 1];
                a2 += wv * rw[kx + 2];
                a3 += wv * rw[kx + 3];
            }
        }
        float4 outv;
        outv.x = mv0 * a0;
        outv.y = mv1 * a1;
        outv.z = mv2 * a2;
        outv.w = mv3 * a3;
        *reinterpret_cast<float4*>(&dst[y * 64 + x0]) = outv;
    }
}

// ---------------- K3/K4: 3x3 conv split-K partial (round-8 proven form) ------
// pack2 weights, KCc=8 synchronous loads, __launch_bounds__(.,3).
template <int KOT, int KOTH, int ROWS, int CIN, int KOTOT, int NSPLIT, int SEL>
__global__ __launch_bounds__(KOTH * 32, 3) void k_conv3(const float* __restrict__ wgt) {
    constexpr int TN = 2 * ROWS;
    constexpr int KCc = 8;
    constexpr int IW = 66;
    constexpr int IR = ROWS + 2;
    constexpr int NTHR = KOTH * 32;
    constexpr int CBT = 64 / TN;
    constexpr int CPS = (((CIN + NSPLIT - 1) / NSPLIT) + KCc - 1) / KCc * KCc;

    __shared__ float in_s[KCc * IR * IW];
    __shared__ float w_s[KCc * 9][KOT];

    const float* in = (SEL == 0) ? g_attvol : g_h1;

    int koB = blockIdx.x, rg = blockIdx.y;
    int b = blockIdx.z / NSPLIT;
    int s = blockIdx.z % NSPLIT;
    int cbeg = s * CPS;
    int cend = (cbeg + CPS < CIN) ? (cbeg + CPS) : CIN;

    int y0 = rg * ROWS;
    int tid = threadIdx.x;
    int kot = tid >> 5, pt = tid & 31;
    int r = pt / CBT, cb = pt % CBT;

    unsigned long long acc[4][TN];
#pragma unroll
    for (int mp = 0; mp < 4; mp++)
#pragma unroll
        for (int j = 0; j < TN; j++) acc[mp][j] = 0ull;

    const float* inb = in + (size_t)b * CIN * HWSZ;

    for (int ci0 = cbeg; ci0 < cend; ci0 += KCc) {
        __syncthreads();
        for (int i = tid; i < KCc * IR * IW; i += NTHR) {
            int cc = i / (IR * IW);
            int rem = i - cc * (IR * IW);
            int rr = rem / IW;
            int c = rem - rr * IW;
            int gy = y0 + rr - 1, gx = c - 1, ci = ci0 + cc;
            float v = 0.f;
            if (ci < cend && gy >= 0 && gy < 64 && gx >= 0 && gx < 64)
                v = inb[((size_t)ci * 64 + gy) * 64 + gx];
            in_s[i] = v;
        }
        for (int i = tid; i < KCc * 9 * KOT; i += NTHR) {
            int kos = i / (KCc * 9);
            int kk = i - kos * (KCc * 9);
            int cc = kk / 9;
            int q = kk - cc * 9;
            int ko = koB * KOT + kos, ci = ci0 + cc;
            float v = 0.f;
            if (ko < KOTOT && ci < cend)
                v = wgt[((size_t)ko * CIN + ci) * 9 + q];
            w_s[kk][kos] = v;
        }
        __syncthreads();

#pragma unroll 1
        for (int cc = 0; cc < KCc; cc++) {
#pragma unroll
            for (int ky = 0; ky < 3; ky++) {
                const float* irow = &in_s[(cc * IR + r + ky) * IW + cb * TN];
                unsigned long long rb[TN + 2];
#pragma unroll
                for (int j = 0; j < TN + 2; j++) rb[j] = bcast2(irow[j]);
#pragma unroll
                for (int kx = 0; kx < 3; kx++) {
                    int kk = cc * 9 + ky * 3 + kx;
                    const float4* wp = reinterpret_cast<const float4*>(&w_s[kk][kot * 8]);
                    float4 wa = wp[0], wb = wp[1];
                    unsigned long long w2[4];
                    w2[0] = pack2(wa.x, wa.y);
                    w2[1] = pack2(wa.z, wa.w);
                    w2[2] = pack2(wb.x, wb.y);
                    w2[3] = pack2(wb.z, wb.w);
#pragma unroll
                    for (int mp = 0; mp < 4; mp++)
#pragma unroll
                        for (int j = 0; j < TN; j++)
                            fma2(acc[mp][j], w2[mp], rb[kx + j]);
                }
            }
        }
    }

    float* pout = g_part[s];
#pragma unroll
    for (int mp = 0; mp < 4; mp++) {
        int ko0 = koB * KOT + kot * 8 + 2 * mp;
#pragma unroll
        for (int half = 0; half < 2; half++) {
            int ko = ko0 + half;
            if (ko < KOTOT) {
                float* op = pout + (((size_t)b * KOTOT + ko) * 64 + (y0 + r)) * 64 + cb * TN;
#pragma unroll
                for (int j = 0; j < TN; j++) {
                    float2 v = *reinterpret_cast<float2*>(&acc[mp][j]);
                    op[j] = half ? v.y : v.x;
                }
            }
        }
    }
}

// ---------------- combine: sum NSPLIT partials + bias + relu -------------------
template <int KOTOT, int NSPLIT>
__global__ __launch_bounds__(256) void k_combine(const float* __restrict__ bias,
                                                 float* __restrict__ dout) {
    int idx4 = blockIdx.x * blockDim.x + threadIdx.x;
    int total4 = BATCH * KOTOT * HWSZ / 4;
    if (idx4 >= total4) return;
    int ko = ((idx4 * 4) >> 12) % KOTOT;
    float4 a = reinterpret_cast<const float4*>(g_part[0])[idx4];
#pragma unroll
    for (int s = 1; s < NSPLIT; s++) {
        float4 p = reinterpret_cast<const float4*>(g_part[s])[idx4];
        a.x += p.x; a.y += p.y; a.z += p.z; a.w += p.w;
    }
    float bv = bias[ko];
    float4 v;
    v.x = fmaxf(a.x + bv, 0.f);
    v.y = fmaxf(a.y + bv, 0.f);
    v.z = fmaxf(a.z + bv, 0.f);
    v.w = fmaxf(a.w + bv, 0.f);
    reinterpret_cast<float4*>(dout)[idx4] = v;
}

// ---------------- launch ------------------------------------------------------
extern "C" void kernel_launch(void* const* d_in, const int* in_sizes, int n_in,
                              void* d_out, int out_size) {
    const float* f1    = (const float*)d_in[0];
    const float* f2    = (const float*)d_in[1];
    const float* att_w = (const float*)d_in[2];
    const float* att_b = (const float*)d_in[3];
    const float* a1w   = (const float*)d_in[4];
    const float* a1b   = (const float*)d_in[5];
    const float* a2w   = (const float*)d_in[6];
    const float* a2b   = (const float*)d_in[7];
    float* out = (float*)d_out;

    k_rnorm<<<BATCH * HWSZ / 256, 256>>>(f1);

    // cost volume: 2-way channel split, 272-thread blocks (round-8 form)
    dim3 gcv(8, 8, BATCH * 2);
    k_costvol<<<gcv, 272>>>(f1, f2);

    // depthwise + gate with fused costvol combine
    k_dw<<<BATCH * NCC, 256>>>(att_w, att_b);

    // conv1: 289 -> 144, KOT=48, ROWS=4 (TN=8), 4-way split-K, OCC=3 (proven)
    dim3 g1(3, 16, BATCH * 4);
    k_conv3<48, 6, 4, NCC, KO1, 4, 0><<<g1, 192>>>(a1w);
    {
        float* h1p = nullptr;
        cudaGetSymbolAddress((void**)&h1p, g_h1);
        int total4 = BATCH * KO1 * HWSZ / 4;
        k_combine<KO1, 4><<<(total4 + 255) / 256, 256>>>(a1b, h1p);
    }

    // conv2: 144 -> 49, KOT=56, ROWS=4 (TN=8), 6-way split-K (24 ch each)
    // Same high-intensity shape as conv1; 384 blocks, 21 warps/SM.
    dim3 g2(1, 16, BATCH * 6);
    k_conv3<56, 7, 4, KO1, KO2, 6, 1><<<g2, 224>>>(a2w);
    {
        int total4 = BATCH * KO2 * HWSZ / 4;
        k_combine<KO2, 6><<<(total4 + 255) / 256, 256>>>(a2b, out);
    }
}

// round 17
// speedup vs baseline: 1.0962x; 1.0962x over previous
#include <cuda_runtime.h>
#include <math.h>

#define BATCH 4
#define CCH   256
#define HH    64
#define WW    64
#define HWSZ  4096
#define NCC   289   // 17*17 cost-volume channels
#define KO1   144
#define KO2   49

// ---------------- scratch (device globals; no runtime alloc) ----------------
__device__ float g_rnorm[BATCH * HWSZ];             // 1/(||f1||*256)
__device__ float g_cvpart[2][BATCH * NCC * HWSZ];   // costvol raw partials
__device__ float g_attvol[BATCH * NCC * HWSZ];      // match_vol * att
__device__ float g_h1[BATCH * KO1 * HWSZ];          // after agg1 conv + relu
__device__ float g_part[4][BATCH * KO1 * HWSZ];     // conv split-K partials

// packed fp32x2 FMA: acc += a * b (elementwise on both 32-bit lanes)
__device__ __forceinline__ void fma2(unsigned long long& acc,
                                     unsigned long long a,
                                     unsigned long long b) {
    asm("fma.rn.f32x2 %0, %1, %2, %0;" : "+l"(acc) : "l"(a), "l"(b));
}
__device__ __forceinline__ unsigned long long bcast2(float v) {
    unsigned long long r;
    asm("mov.b64 %0, {%1, %1};" : "=l"(r) : "f"(v));
    return r;
}
__device__ __forceinline__ unsigned long long pack2(float lo, float hi) {
    unsigned long long r;
    asm("mov.b64 %0, {%1, %2};" : "=l"(r) : "f"(lo), "f"(hi));
    return r;
}

// ---------------- K0: per-pixel inverse norm of f1 --------------------------
__global__ void k_rnorm(const float* __restrict__ f1) {
    int p = blockIdx.x * blockDim.x + threadIdx.x;
    int b = p >> 12;
    int sp = p & 4095;
    const float* base = f1 + (size_t)b * CCH * HWSZ + sp;
    float s = 0.f;
#pragma unroll 8
    for (int c = 0; c < CCH; c++) {
        float v = base[c * HWSZ];
        s += v * v;
    }
    float n = fmaxf(sqrtf(s), 1e-12f);
    g_rnorm[p] = 1.f / (n * 256.f);
}

// ---------------- K1: cost volume raw partials (round-8 core) ----------------
// 272 threads, 2-way channel split, f32x2 main loop (proven). NEW: epilogue
// transposes accumulators through smem and writes coalesced 32B sectors
// (old path: 25% sector efficiency on 68 scattered STG per thread).
#define CV_KC 16
__global__ __launch_bounds__(272) void k_costvol(const float* __restrict__ f1,
                                                 const float* __restrict__ f2) {
    __shared__ float smem_all[CV_KC * 64 + CV_KC * 600];   // x1s | x2s, reused by epilogue
    float* x1s = smem_all;                  // [cc][pos] 16*64
    float* x2s = smem_all + CV_KC * 64;     // [cc][row(24)][col stride 25]

    int tw = blockIdx.x, th = blockIdx.y;
    int b  = blockIdx.z >> 1;
    int s  = blockIdx.z & 1;
    int h0 = th * 8, w0 = tw * 8;

    int t   = threadIdx.x;
    int oj  = t >> 4;
    int pg  = t & 15;
    int py  = pg >> 1;
    int px0 = pg & 1;

    unsigned long long acc2[4][8];
    float accS[4];
#pragma unroll
    for (int j = 0; j < 4; j++) {
        accS[j] = 0.f;
#pragma unroll
        for (int p = 0; p < 8; p++) acc2[j][p] = 0ull;
    }

    int clo = s * (CCH / 2), chi = clo + CCH / 2;
    for (int c0 = clo; c0 < chi; c0 += CV_KC) {
        __syncthreads();
        for (int i = t; i < CV_KC * 64; i += 272) {
            int cc = i >> 6, pp = i & 63;
            x1s[i] = f1[(((size_t)b * CCH + c0 + cc) * 64 + h0 + (pp >> 3)) * 64 + w0 + (pp & 7)];
        }
        for (int i = t; i < CV_KC * 24 * 24; i += 272) {
            int cc = i / 576;
            int rem = i - cc * 576;
            int r = rem / 24;
            int cx = rem - r * 24;
            int gh = h0 + r - 8, gw = w0 + cx - 8;
            float v = 0.f;
            if (gh >= 0 && gh < 64 && gw >= 0 && gw < 64)
                v = f2[(((size_t)b * CCH + c0 + cc) * 64 + gh) * 64 + gw];
            x2s[cc * 600 + r * 25 + cx] = v;
        }
        __syncthreads();

#pragma unroll 2
        for (int cc = 0; cc < CV_KC; cc++) {
            float x1v[4];
            unsigned long long x1b[4];
#pragma unroll
            for (int j = 0; j < 4; j++) {
                x1v[j] = x1s[cc * 64 + py * 8 + px0 + 2 * j];
                x1b[j] = bcast2(x1v[j]);
            }
            const float* row = &x2s[cc * 600 + (py + oj) * 25 + px0];
            float rv[23];
#pragma unroll
            for (int i = 0; i < 23; i++) rv[i] = row[i];
            unsigned long long rp[11];
#pragma unroll
            for (int k = 0; k < 11; k++) rp[k] = pack2(rv[2 * k], rv[2 * k + 1]);
#pragma unroll
            for (int j = 0; j < 4; j++) {
#pragma unroll
                for (int p = 0; p < 8; p++)
                    fma2(acc2[j][p], x1b[j], rp[j + p]);
                accS[j] += x1v[j] * rv[2 * j + 16];
            }
        }
    }

    // ---- epilogue: smem transpose + coalesced stores ----
    // Pass 1: oi 0..8 (buf row = oj*9 + oi, 153 rows x 65 stride)
    // Pass 2: oi 9..16 (buf row = oj*8 + oi-9, 136 rows x 65 stride)
    float* pout = g_cvpart[s];
    {
        __syncthreads();
#pragma unroll
        for (int j = 0; j < 4; j++) {
            int pix = py * 8 + px0 + 2 * j;
#pragma unroll
            for (int p = 0; p < 4; p++) {
                float2 v = *reinterpret_cast<float2*>(&acc2[j][p]);
                smem_all[(oj * 9 + 2 * p) * 65 + pix]     = v.x;
                smem_all[(oj * 9 + 2 * p + 1) * 65 + pix] = v.y;
            }
            float2 v4 = *reinterpret_cast<float2*>(&acc2[j][4]);
            smem_all[(oj * 9 + 8) * 65 + pix] = v4.x;   // oi = 8
        }
        __syncthreads();
        for (int i = t; i < 153 * 64; i += 272) {
            int row = i >> 6, col = i & 63;
            int ojr = row / 9, oir = row - 9 * ojr;
            int o = ojr * 17 + oir;
            pout[((size_t)(b * NCC + o) << 12) + (h0 + (col >> 3)) * 64 + w0 + (col & 7)] =
                smem_all[row * 65 + col];
        }
        __syncthreads();
#pragma unroll
        for (int j = 0; j < 4; j++) {
            int pix = py * 8 + px0 + 2 * j;
            float2 v4 = *reinterpret_cast<float2*>(&acc2[j][4]);
            smem_all[(oj * 8 + 0) * 65 + pix] = v4.y;   // oi = 9
#pragma unroll
            for (int p = 5; p < 8; p++) {
                float2 v = *reinterpret_cast<float2*>(&acc2[j][p]);
                smem_all[(oj * 8 + 2 * p - 9) * 65 + pix] = v.x;   // oi = 2p
                smem_all[(oj * 8 + 2 * p - 8) * 65 + pix] = v.y;   // oi = 2p+1
            }
            smem_all[(oj * 8 + 7) * 65 + pix] = accS[j];           // oi = 16
        }
        __syncthreads();
        for (int i = t; i < 136 * 64; i += 272) {
            int row = i >> 6, col = i & 63;
            int ojr = row >> 3, oir = row & 7;
            int o = ojr * 17 + 9 + oir;
            pout[((size_t)(b * NCC + o) << 12) + (h0 + (col >> 3)) * 64 + w0 + (col & 7)] =
                smem_all[row * 65 + col];
        }
    }
}

// ---------------- K2: depthwise 7x7 attention + gate (fused cv combine) ------
__global__ __launch_bounds__(256) void k_dw(const float* __restrict__ w7,
                                            const float* __restrict__ b7) {
    __shared__ float tile[70 * 70];
    __shared__ float wsh[49];
    int bo = blockIdx.x;
    int o = bo % NCC;
    int b = bo / NCC;
    const float* p0 = g_cvpart[0] + (size_t)bo * HWSZ;
    const float* p1 = g_cvpart[1] + (size_t)bo * HWSZ;
    const float* rn = g_rnorm + ((size_t)b << 12);
    int t = threadIdx.x;

    for (int i = t; i < 4900; i += 256) {
        int r = i / 70, c = i - r * 70;
        int gy = r - 3, gx = c - 3;
        float v = 0.f;
        if (gy >= 0 && gy < 64 && gx >= 0 && gx < 64) {
            int idx = gy * 64 + gx;
            v = (p0[idx] + p1[idx]) * rn[idx];
            v = v > 0.f ? v : 0.1f * v;
        }
        tile[i] = v;
    }
    if (t < 49) wsh[t] = w7[o * 49 + t];
    __syncthreads();

    float bv = b7[o];
    float* dst = g_attvol + (size_t)bo * HWSZ;
#pragma unroll
    for (int gg = 0; gg < 4; gg++) {
        int g = gg * 256 + t;
        int y = g >> 4;
        int x0 = (g & 15) * 4;
        float a0 = bv, a1 = bv, a2 = bv, a3 = bv;
        float mv0, mv1, mv2, mv3;
#pragma unroll
        for (int ky = 0; ky < 7; ky++) {
            const float* row = &tile[(y + ky) * 70 + x0];
            float rw[10];
#pragma unroll
            for (int i = 0; i < 10; i++) rw[i] = row[i];
            if (ky == 3) { mv0 = rw[3]; mv1 = rw[4]; mv2 = rw[5]; mv3 = rw[6]; }
#pragma unroll
            for (int kx = 0; kx < 7; kx++) {
                float wv = wsh[ky * 7 + kx];
                a0 += wv * rw[kx];
                a1 += wv * rw[kx + 1];
                a2 += wv * rw[kx + 2];
                a3 += wv * rw[kx + 3];
            }
        }
        float4 outv;
        outv.x = mv0 * a0;
        outv.y = mv1 * a1;
        outv.z = mv2 * a2;
        outv.w = mv3 * a3;
        *reinterpret_cast<float4*>(&dst[y * 64 + x0]) = outv;
    }
}

// ---------------- K3/K4: 3x3 conv split-K partial (round-8 proven form) ------
template <int KOT, int KOTH, int ROWS, int CIN, int KOTOT, int NSPLIT, int SEL>
__global__ __launch_bounds__(KOTH * 32, 3) void k_conv3(const float* __restrict__ wgt) {
    constexpr int TN = 2 * ROWS;
    constexpr int KCc = 8;
    constexpr int IW = 66;
    constexpr int IR = ROWS + 2;
    constexpr int NTHR = KOTH * 32;
    constexpr int CBT = 64 / TN;
    constexpr int CPS = (((CIN + NSPLIT - 1) / NSPLIT) + KCc - 1) / KCc * KCc;

    __shared__ float in_s[KCc * IR * IW];
    __shared__ float w_s[KCc * 9][KOT];

    const float* in = (SEL == 0) ? g_attvol : g_h1;

    int koB = blockIdx.x, rg = blockIdx.y;
    int b = blockIdx.z / NSPLIT;
    int s = blockIdx.z % NSPLIT;
    int cbeg = s * CPS;
    int cend = (cbeg + CPS < CIN) ? (cbeg + CPS) : CIN;

    int y0 = rg * ROWS;
    int tid = threadIdx.x;
    int kot = tid >> 5, pt = tid & 31;
    int r = pt / CBT, cb = pt % CBT;

    unsigned long long acc[4][TN];
#pragma unroll
    for (int mp = 0; mp < 4; mp++)
#pragma unroll
        for (int j = 0; j < TN; j++) acc[mp][j] = 0ull;

    const float* inb = in + (size_t)b * CIN * HWSZ;

    for (int ci0 = cbeg; ci0 < cend; ci0 += KCc) {
        __syncthreads();
        for (int i = tid; i < KCc * IR * IW; i += NTHR) {
            int cc = i / (IR * IW);
            int rem = i - cc * (IR * IW);
            int rr = rem / IW;
            int c = rem - rr * IW;
            int gy = y0 + rr - 1, gx = c - 1, ci = ci0 + cc;
            float v = 0.f;
            if (ci < cend && gy >= 0 && gy < 64 && gx >= 0 && gx < 64)
                v = inb[((size_t)ci * 64 + gy) * 64 + gx];
            in_s[i] = v;
        }
        for (int i = tid; i < KCc * 9 * KOT; i += NTHR) {
            int kos = i / (KCc * 9);
            int kk = i - kos * (KCc * 9);
            int cc = kk / 9;
            int q = kk - cc * 9;
            int ko = koB * KOT + kos, ci = ci0 + cc;
            float v = 0.f;
            if (ko < KOTOT && ci < cend)
                v = wgt[((size_t)ko * CIN + ci) * 9 + q];
            w_s[kk][kos] = v;
        }
        __syncthreads();

#pragma unroll 1
        for (int cc = 0; cc < KCc; cc++) {
#pragma unroll
            for (int ky = 0; ky < 3; ky++) {
                const float* irow = &in_s[(cc * IR + r + ky) * IW + cb * TN];
                unsigned long long rb[TN + 2];
#pragma unroll
                for (int j = 0; j < TN + 2; j++) rb[j] = bcast2(irow[j]);
#pragma unroll
                for (int kx = 0; kx < 3; kx++) {
                    int kk = cc * 9 + ky * 3 + kx;
                    const float4* wp = reinterpret_cast<const float4*>(&w_s[kk][kot * 8]);
                    float4 wa = wp[0], wb = wp[1];
                    unsigned long long w2[4];
                    w2[0] = pack2(wa.x, wa.y);
                    w2[1] = pack2(wa.z, wa.w);
                    w2[2] = pack2(wb.x, wb.y);
                    w2[3] = pack2(wb.z, wb.w);
#pragma unroll
                    for (int mp = 0; mp < 4; mp++)
#pragma unroll
                        for (int j = 0; j < TN; j++)
                            fma2(acc[mp][j], w2[mp], rb[kx + j]);
                }
            }
        }
    }

    float* pout = g_part[s];
#pragma unroll
    for (int mp = 0; mp < 4; mp++) {
        int ko0 = koB * KOT + kot * 8 + 2 * mp;
#pragma unroll
        for (int half = 0; half < 2; half++) {
            int ko = ko0 + half;
            if (ko < KOTOT) {
                float* op = pout + (((size_t)b * KOTOT + ko) * 64 + (y0 + r)) * 64 + cb * TN;
#pragma unroll
                for (int j = 0; j < TN; j++) {
                    float2 v = *reinterpret_cast<float2*>(&acc[mp][j]);
                    op[j] = half ? v.y : v.x;
                }
            }
        }
    }
}

// ---------------- combine: sum NSPLIT partials + bias + relu -------------------
template <int KOTOT, int NSPLIT>
__global__ __launch_bounds__(256) void k_combine(const float* __restrict__ bias,
                                                 float* __restrict__ dout) {
    int idx4 = blockIdx.x * blockDim.x + threadIdx.x;
    int total4 = BATCH * KOTOT * HWSZ / 4;
    if (idx4 >= total4) return;
    int ko = ((idx4 * 4) >> 12) % KOTOT;
    float4 a = reinterpret_cast<const float4*>(g_part[0])[idx4];
#pragma unroll
    for (int s = 1; s < NSPLIT; s++) {
        float4 p = reinterpret_cast<const float4*>(g_part[s])[idx4];
        a.x += p.x; a.y += p.y; a.z += p.z; a.w += p.w;
    }
    float bv = bias[ko];
    float4 v;
    v.x = fmaxf(a.x + bv, 0.f);
    v.y = fmaxf(a.y + bv, 0.f);
    v.z = fmaxf(a.z + bv, 0.f);
    v.w = fmaxf(a.w + bv, 0.f);
    reinterpret_cast<float4*>(dout)[idx4] = v;
}

// ---------------- launch ------------------------------------------------------
extern "C" void kernel_launch(void* const* d_in, const int* in_sizes, int n_in,
                              void* d_out, int out_size) {
    const float* f1    = (const float*)d_in[0];
    const float* f2    = (const float*)d_in[1];
    const float* att_w = (const float*)d_in[2];
    const float* att_b = (const float*)d_in[3];
    const float* a1w   = (const float*)d_in[4];
    const float* a1b   = (const float*)d_in[5];
    const float* a2w   = (const float*)d_in[6];
    const float* a2b   = (const float*)d_in[7];
    float* out = (float*)d_out;

    k_rnorm<<<BATCH * HWSZ / 256, 256>>>(f1);

    // cost volume: 2-way channel split, coalesced-store epilogue
    dim3 gcv(8, 8, BATCH * 2);
    k_costvol<<<gcv, 272>>>(f1, f2);

    // depthwise + gate with fused costvol combine
    k_dw<<<BATCH * NCC, 256>>>(att_w, att_b);

    // conv1: 289 -> 144, KOT=48, ROWS=4 (TN=8), 4-way split-K, OCC=3 (proven)
    dim3 g1(3, 16, BATCH * 4);
    k_conv3<48, 6, 4, NCC, KO1, 4, 0><<<g1, 192>>>(a1w);
    {
        float* h1p = nullptr;
        cudaGetSymbolAddress((void**)&h1p, g_h1);
        int total4 = BATCH * KO1 * HWSZ / 4;
        k_combine<KO1, 4><<<(total4 + 255) / 256, 256>>>(a1b, h1p);
    }

    // conv2: 144 -> 49, KOT=56, ROWS=2 (TN=4), 3-way split-K, OCC=3 (proven)
    dim3 g2(1, 32, BATCH * 3);
    k_conv3<56, 7, 2, KO1, KO2, 3, 1><<<g2, 224>>>(a2w);
    {
        int total4 = BATCH * KO2 * HWSZ / 4;
        k_combine<KO2, 3><<<(total4 + 255) / 256, 256>>>(a2b, out);
    }
}